// round 14
// baseline (speedup 1.0000x reference)
#include <cuda_runtime.h>
#include <cuda_bf16.h>
#include <cstdint>

// Problem constants
#define Bn 8
#define Tn 512
#define Dn 1024
#define Hn 16
#define DHn 64
#define FKP 2048   // physical operand width: [hi | lo]

// Scratch (allocation-free __device__ globals; uint4 => 16B alignment)
__device__ uint4 g_A4[(size_t)Bn * Tn * FKP * 2 / 16];  // bf16 A [4096][2048]: hi|lo
__device__ uint4 g_B4[(size_t)Dn * FKP * 2 / 16];       // bf16 B [1024][2048]: hi|lo (Wf^T)
// Attention operands (bf16), per (b,h):
__device__ uint4 g_Qh4[Bn * Hn * Tn * DHn * 2 / 16];   // [bh][t][64] hi, pre-scaled 1/8
__device__ uint4 g_Ql4[Bn * Hn * Tn * DHn * 2 / 16];   // lo
__device__ uint4 g_Kh4[Bn * Hn * Tn * DHn * 2 / 16];   // [bh][t][64]
__device__ uint4 g_Kl4[Bn * Hn * Tn * DHn * 2 / 16];
__device__ uint4 g_Vh4[Bn * Hn * Tn * DHn * 2 / 16];   // [bh][d][t]  (transposed)
__device__ uint4 g_Vl4[Bn * Hn * Tn * DHn * 2 / 16];

__device__ __forceinline__ uint32_t smem_u32(const void* p) {
    uint32_t a;
    asm("{ .reg .u64 t; cvta.to.shared.u64 t, %1; cvt.u32.u64 %0, t; }" : "=r"(a) : "l"(p));
    return a;
}
__device__ __forceinline__ uint32_t pack_bf16(float a, float b) {
    __nv_bfloat162 t = __floats2bfloat162_rn(a, b);
    return *(uint32_t*)&t;
}
__device__ __forceinline__ void mma_bf16(float* c, const uint32_t* a, const uint32_t* b) {
    asm volatile(
        "mma.sync.aligned.m16n8k16.row.col.f32.bf16.bf16.f32 "
        "{%0,%1,%2,%3}, {%4,%5,%6,%7}, {%8,%9}, {%0,%1,%2,%3};"
        : "+f"(c[0]), "+f"(c[1]), "+f"(c[2]), "+f"(c[3])
        : "r"(a[0]), "r"(a[1]), "r"(a[2]), "r"(a[3]), "r"(b[0]), "r"(b[1]));
}
#define LDSM_X4(r, addr) \
    asm volatile("ldmatrix.sync.aligned.m8n8.x4.shared.b16 {%0,%1,%2,%3}, [%4];" \
                 : "=r"((r)[0]), "=r"((r)[1]), "=r"((r)[2]), "=r"((r)[3]) : "r"(addr))
#define CP16(dst, src) \
    asm volatile("cp.async.cg.shared.global [%0], [%1], 16;" :: "r"(dst), "l"(src))
#define CP_COMMIT() asm volatile("cp.async.commit_group;" ::: "memory")
#define CP_WAIT0()  asm volatile("cp.async.wait_group 0;" ::: "memory")

// ---------------------------------------------------------------------------
// Kernel 1: per-head QKV projections -> split-bf16 operands.
// ---------------------------------------------------------------------------
__global__ __launch_bounds__(256) void qkv_kernel(
    const float* __restrict__ X,
    const float* __restrict__ Wq, const float* __restrict__ bq,
    const float* __restrict__ Wk, const float* __restrict__ bk,
    const float* __restrict__ Wv, const float* __restrict__ bv)
{
    const int bh = blockIdx.x;
    const int b = bh >> 4;
    const int h = bh & 15;
    const int t0 = blockIdx.y * 64;
    const int tid = threadIdx.x;

    __shared__ float XsT[64][68];
    __shared__ float Ws[64][64];

#pragma unroll
    for (int i = 0; i < 4; i++) {
        int idx = tid + i * 256;
        int r = idx >> 4;
        int d4 = (idx & 15) << 2;
        float4 xv = *(const float4*)(X + (size_t)(b * Tn + t0 + r) * Dn + h * DHn + d4);
        XsT[d4 + 0][r] = xv.x; XsT[d4 + 1][r] = xv.y;
        XsT[d4 + 2][r] = xv.z; XsT[d4 + 3][r] = xv.w;
    }

    const int tx = tid & 15, ty = tid >> 4;
    const int r0 = ty * 4, c0 = tx * 4;

    const float* Wsrc[3] = { Wq + h * DHn * DHn, Wk + h * DHn * DHn, Wv + h * DHn * DHn };
    const float* bsrc[3] = { bq + h * DHn, bk + h * DHn, bv + h * DHn };

    for (int w = 0; w < 3; w++) {
        __syncthreads();
#pragma unroll
        for (int i = 0; i < 4; i++) {
            int idx = tid + i * 256;
            int d = idx >> 4;
            int e4 = (idx & 15) << 2;
            *(float4*)&Ws[d][e4] = *(const float4*)(Wsrc[w] + d * DHn + e4);
        }
        __syncthreads();

        float acc[4][4];
        float4 bv4 = *(const float4*)(bsrc[w] + c0);
#pragma unroll
        for (int i = 0; i < 4; i++) {
            acc[i][0] = bv4.x; acc[i][1] = bv4.y; acc[i][2] = bv4.z; acc[i][3] = bv4.w;
        }
#pragma unroll 8
        for (int d = 0; d < 64; d++) {
            float4 xr = *(float4*)&XsT[d][r0];
            float4 wr = *(float4*)&Ws[d][c0];
            float xa[4] = { xr.x, xr.y, xr.z, xr.w };
            float wa[4] = { wr.x, wr.y, wr.z, wr.w };
#pragma unroll
            for (int i = 0; i < 4; i++)
#pragma unroll
                for (int j = 0; j < 4; j++)
                    acc[i][j] += xa[i] * wa[j];
        }

        const float scale = (w == 0) ? 0.125f : 1.0f;
        if (w < 2) {
            __nv_bfloat16* dh = (__nv_bfloat16*)(w == 0 ? g_Qh4 : g_Kh4)
                                + ((size_t)bh * Tn + t0 + r0) * DHn + c0;
            __nv_bfloat16* dl = (__nv_bfloat16*)(w == 0 ? g_Ql4 : g_Kl4)
                                + ((size_t)bh * Tn + t0 + r0) * DHn + c0;
#pragma unroll
            for (int i = 0; i < 4; i++) {
#pragma unroll
                for (int j2 = 0; j2 < 2; j2++) {
                    float v0 = acc[i][j2 * 2 + 0] * scale;
                    float v1 = acc[i][j2 * 2 + 1] * scale;
                    __nv_bfloat16 h0 = __float2bfloat16_rn(v0);
                    __nv_bfloat16 h1 = __float2bfloat16_rn(v1);
                    __nv_bfloat162 hp; hp.x = h0; hp.y = h1;
                    __nv_bfloat162 lp;
                    lp.x = __float2bfloat16_rn(v0 - __bfloat162float(h0));
                    lp.y = __float2bfloat16_rn(v1 - __bfloat162float(h1));
                    *(__nv_bfloat162*)(dh + (size_t)i * DHn + j2 * 2) = hp;
                    *(__nv_bfloat162*)(dl + (size_t)i * DHn + j2 * 2) = lp;
                }
            }
        } else {
            __nv_bfloat16* vh = (__nv_bfloat16*)g_Vh4 + (size_t)bh * DHn * Tn;
            __nv_bfloat16* vl = (__nv_bfloat16*)g_Vl4 + (size_t)bh * DHn * Tn;
#pragma unroll
            for (int i = 0; i < 4; i++)
#pragma unroll
                for (int j = 0; j < 4; j++) {
                    float v = acc[i][j];
                    __nv_bfloat16 hi = __float2bfloat16_rn(v);
                    vh[(size_t)(c0 + j) * Tn + t0 + r0 + i] = hi;
                    vl[(size_t)(c0 + j) * Tn + t0 + r0 + i] =
                        __float2bfloat16_rn(v - __bfloat162float(hi));
                }
        }
    }
}

// ---------------------------------------------------------------------------
// Kernel 2: tensor-core flash attention (x4 B-frag loads).
// grid = (B*H, T/64), block = 128 (4 warps x m16 queries).
// Writes split-bf16 A rows for the fusion GEMM: hi at col, lo at 1024+col.
// ---------------------------------------------------------------------------
__global__ __launch_bounds__(128) void attn_mma_kernel(const int* __restrict__ mask)
{
    const int bh = blockIdx.x;
    const int b = bh >> 4;
    const int h = bh & 15;
    const int q0 = blockIdx.y * 64;
    const int tid = threadIdx.x;
    const int wid = tid >> 5;
    const int lane = tid & 31;
    const int wm = wid * 16;

    __shared__ __nv_bfloat16 Khs[64][72];
    __shared__ __nv_bfloat16 Kls[64][72];
    __shared__ __nv_bfloat16 Vhs[64][72];
    __shared__ __nv_bfloat16 Vls[64][72];
    __shared__ float msk[64];

    // ---- stage Q tile into Khs/Kls, extract A fragments ----
    {
        const __nv_bfloat16* Qh = (const __nv_bfloat16*)g_Qh4 + ((size_t)bh * Tn + q0) * DHn;
        const __nv_bfloat16* Ql = (const __nv_bfloat16*)g_Ql4 + ((size_t)bh * Tn + q0) * DHn;
#pragma unroll
        for (int i = 0; i < 4; i++) {
            int idx = tid + i * 128;
            int row = idx >> 3;
            int c = idx & 7;
            *(uint4*)&Khs[row][c * 8] = *(const uint4*)(Qh + row * DHn + c * 8);
            *(uint4*)&Kls[row][c * 8] = *(const uint4*)(Ql + row * DHn + c * 8);
        }
    }
    __syncthreads();

    uint32_t qh[4][4], ql[4][4];
#pragma unroll
    for (int kt = 0; kt < 4; kt++) {
        uint32_t a0 = smem_u32(&Khs[wm + (lane & 15)][kt * 16 + (lane >> 4) * 8]);
        LDSM_X4(qh[kt], a0);
        uint32_t a1 = smem_u32(&Kls[wm + (lane & 15)][kt * 16 + (lane >> 4) * 8]);
        LDSM_X4(ql[kt], a1);
    }

    float O[8][4];
#pragma unroll
    for (int nt = 0; nt < 8; nt++)
#pragma unroll
        for (int r = 0; r < 4; r++) O[nt][r] = 0.f;
    float m0 = -1e30f, m1 = -1e30f, l0 = 0.f, l1 = 0.f;

    const __nv_bfloat16* Khg = (const __nv_bfloat16*)g_Kh4 + (size_t)bh * Tn * DHn;
    const __nv_bfloat16* Klg = (const __nv_bfloat16*)g_Kl4 + (size_t)bh * Tn * DHn;
    const __nv_bfloat16* Vhg = (const __nv_bfloat16*)g_Vh4 + (size_t)bh * DHn * Tn;
    const __nv_bfloat16* Vlg = (const __nv_bfloat16*)g_Vl4 + (size_t)bh * DHn * Tn;

    // B-frag x4 address pieces (two n-tiles per ldmatrix)
    const int brow = ((lane >> 4) & 1) * 8 + (lane & 7);
    const int bkof = ((lane >> 3) & 1) * 8;

    for (int kt0 = 0; kt0 < 8; kt0++) {
        const int t0k = kt0 * 64;
        __syncthreads();
#pragma unroll
        for (int i = 0; i < 4; i++) {
            int idx = tid + i * 128;
            int row = idx >> 3;
            int c = idx & 7;
            *(uint4*)&Khs[row][c * 8] = *(const uint4*)(Khg + (size_t)(t0k + row) * DHn + c * 8);
            *(uint4*)&Kls[row][c * 8] = *(const uint4*)(Klg + (size_t)(t0k + row) * DHn + c * 8);
            *(uint4*)&Vhs[row][c * 8] = *(const uint4*)(Vhg + (size_t)row * Tn + t0k + c * 8);
            *(uint4*)&Vls[row][c * 8] = *(const uint4*)(Vlg + (size_t)row * Tn + t0k + c * 8);
        }
        if (tid < 64) msk[tid] = (mask[b * Tn + t0k + tid] > 0) ? 3.0e38f : -1e9f;
        __syncthreads();

        // ---- S = Q K^T (3-term, frag-level reuse) ----
        float S[8][4];
#pragma unroll
        for (int nt = 0; nt < 8; nt++)
#pragma unroll
            for (int r = 0; r < 4; r++) S[nt][r] = 0.f;

#pragma unroll
        for (int kt = 0; kt < 4; kt++) {
#pragma unroll
            for (int ntp = 0; ntp < 4; ntp++) {
                uint32_t kh4[4], kl4[4];
                LDSM_X4(kh4, smem_u32(&Khs[ntp * 16 + brow][kt * 16 + bkof]));
                LDSM_X4(kl4, smem_u32(&Kls[ntp * 16 + brow][kt * 16 + bkof]));
                mma_bf16(S[2 * ntp],     qh[kt], kh4 + 0);
                mma_bf16(S[2 * ntp],     ql[kt], kh4 + 0);
                mma_bf16(S[2 * ntp],     qh[kt], kl4 + 0);
                mma_bf16(S[2 * ntp + 1], qh[kt], kh4 + 2);
                mma_bf16(S[2 * ntp + 1], ql[kt], kh4 + 2);
                mma_bf16(S[2 * ntp + 1], qh[kt], kl4 + 2);
            }
        }

        // ---- mask + online softmax ----
        float rm0 = -1e30f, rm1 = -1e30f;
#pragma unroll
        for (int nt = 0; nt < 8; nt++) {
            int c = nt * 8 + 2 * (lane & 3);
            float mk0 = msk[c], mk1 = msk[c + 1];
            S[nt][0] = fminf(S[nt][0], mk0);
            S[nt][1] = fminf(S[nt][1], mk1);
            S[nt][2] = fminf(S[nt][2], mk0);
            S[nt][3] = fminf(S[nt][3], mk1);
            rm0 = fmaxf(rm0, fmaxf(S[nt][0], S[nt][1]));
            rm1 = fmaxf(rm1, fmaxf(S[nt][2], S[nt][3]));
        }
        rm0 = fmaxf(rm0, __shfl_xor_sync(0xffffffffu, rm0, 1));
        rm0 = fmaxf(rm0, __shfl_xor_sync(0xffffffffu, rm0, 2));
        rm1 = fmaxf(rm1, __shfl_xor_sync(0xffffffffu, rm1, 1));
        rm1 = fmaxf(rm1, __shfl_xor_sync(0xffffffffu, rm1, 2));

        float m0n = fmaxf(m0, rm0), m1n = fmaxf(m1, rm1);
        float c0f = __expf(m0 - m0n), c1f = __expf(m1 - m1n);
        l0 *= c0f; l1 *= c1f;
#pragma unroll
        for (int nt = 0; nt < 8; nt++) {
            O[nt][0] *= c0f; O[nt][1] *= c0f;
            O[nt][2] *= c1f; O[nt][3] *= c1f;
        }
        m0 = m0n; m1 = m1n;

        float ps0 = 0.f, ps1 = 0.f;
#pragma unroll
        for (int nt = 0; nt < 8; nt++) {
            S[nt][0] = __expf(S[nt][0] - m0);
            S[nt][1] = __expf(S[nt][1] - m0);
            S[nt][2] = __expf(S[nt][2] - m1);
            S[nt][3] = __expf(S[nt][3] - m1);
            ps0 += S[nt][0] + S[nt][1];
            ps1 += S[nt][2] + S[nt][3];
        }
        l0 += ps0; l1 += ps1;

        // ---- O += P V (3-term; P frags built from S regs) ----
#pragma unroll
        for (int kt = 0; kt < 4; kt++) {
            float p00 = S[2 * kt][0], p01 = S[2 * kt][1], p02 = S[2 * kt][2], p03 = S[2 * kt][3];
            float p10 = S[2 * kt + 1][0], p11 = S[2 * kt + 1][1], p12 = S[2 * kt + 1][2], p13 = S[2 * kt + 1][3];
            __nv_bfloat16 h00 = __float2bfloat16_rn(p00), h01 = __float2bfloat16_rn(p01);
            __nv_bfloat16 h02 = __float2bfloat16_rn(p02), h03 = __float2bfloat16_rn(p03);
            __nv_bfloat16 h10 = __float2bfloat16_rn(p10), h11 = __float2bfloat16_rn(p11);
            __nv_bfloat16 h12 = __float2bfloat16_rn(p12), h13 = __float2bfloat16_rn(p13);
            uint32_t ah[4], al[4];
            { __nv_bfloat162 t; t.x = h00; t.y = h01; ah[0] = *(uint32_t*)&t; }
            { __nv_bfloat162 t; t.x = h02; t.y = h03; ah[1] = *(uint32_t*)&t; }
            { __nv_bfloat162 t; t.x = h10; t.y = h11; ah[2] = *(uint32_t*)&t; }
            { __nv_bfloat162 t; t.x = h12; t.y = h13; ah[3] = *(uint32_t*)&t; }
            al[0] = pack_bf16(p00 - __bfloat162float(h00), p01 - __bfloat162float(h01));
            al[1] = pack_bf16(p02 - __bfloat162float(h02), p03 - __bfloat162float(h03));
            al[2] = pack_bf16(p10 - __bfloat162float(h10), p11 - __bfloat162float(h11));
            al[3] = pack_bf16(p12 - __bfloat162float(h12), p13 - __bfloat162float(h13));
#pragma unroll
            for (int ntp = 0; ntp < 4; ntp++) {
                uint32_t vh4[4], vl4[4];
                LDSM_X4(vh4, smem_u32(&Vhs[ntp * 16 + brow][kt * 16 + bkof]));
                LDSM_X4(vl4, smem_u32(&Vls[ntp * 16 + brow][kt * 16 + bkof]));
                mma_bf16(O[2 * ntp],     ah, vh4 + 0);
                mma_bf16(O[2 * ntp],     al, vh4 + 0);
                mma_bf16(O[2 * ntp],     ah, vl4 + 0);
                mma_bf16(O[2 * ntp + 1], ah, vh4 + 2);
                mma_bf16(O[2 * ntp + 1], al, vh4 + 2);
                mma_bf16(O[2 * ntp + 1], ah, vl4 + 2);
            }
        }
    }

    // ---- epilogue ----
    l0 += __shfl_xor_sync(0xffffffffu, l0, 1);
    l0 += __shfl_xor_sync(0xffffffffu, l0, 2);
    l1 += __shfl_xor_sync(0xffffffffu, l1, 1);
    l1 += __shfl_xor_sync(0xffffffffu, l1, 2);
    const float inv0 = 1.f / l0;
    const float inv1 = 1.f / l1;

    const int row0 = b * Tn + q0 + wm + (lane >> 2);
    const int row1 = row0 + 8;
    __nv_bfloat16* Ap = (__nv_bfloat16*)g_A4;
#pragma unroll
    for (int nt = 0; nt < 8; nt++) {
        const int col = h * DHn + nt * 8 + 2 * (lane & 3);
        float o00 = O[nt][0] * inv0, o01 = O[nt][1] * inv0;
        float o10 = O[nt][2] * inv1, o11 = O[nt][3] * inv1;
        __nv_bfloat16 h00 = __float2bfloat16_rn(o00), h01 = __float2bfloat16_rn(o01);
        __nv_bfloat16 h10 = __float2bfloat16_rn(o10), h11 = __float2bfloat16_rn(o11);
        uint32_t hp0, hp1;
        { __nv_bfloat162 t; t.x = h00; t.y = h01; hp0 = *(uint32_t*)&t; }
        { __nv_bfloat162 t; t.x = h10; t.y = h11; hp1 = *(uint32_t*)&t; }
        uint32_t lp0 = pack_bf16(o00 - __bfloat162float(h00), o01 - __bfloat162float(h01));
        uint32_t lp1 = pack_bf16(o10 - __bfloat162float(h10), o11 - __bfloat162float(h11));
        *(uint32_t*)(Ap + (size_t)row0 * FKP + col)        = hp0;
        *(uint32_t*)(Ap + (size_t)row0 * FKP + 1024 + col) = lp0;
        *(uint32_t*)(Ap + (size_t)row1 * FKP + col)        = hp1;
        *(uint32_t*)(Ap + (size_t)row1 * FKP + 1024 + col) = lp1;
    }
}

// ---------------------------------------------------------------------------
// Kernel 3: build B = split-bf16 transpose of Wf: hi at k, lo at 1024+k.
// ---------------------------------------------------------------------------
__global__ __launch_bounds__(256) void convw_kernel(const float* __restrict__ Wf)
{
    __shared__ float t[32][33];
    const int tx = threadIdx.x & 31, ty = threadIdx.x >> 5;
    const int n0 = blockIdx.x * 32, k0 = blockIdx.y * 32;

#pragma unroll
    for (int r = 0; r < 4; r++)
        t[ty + r * 8][tx] = Wf[(size_t)(k0 + ty + r * 8) * Dn + n0 + tx];
    __syncthreads();

    __nv_bfloat16* Bg = (__nv_bfloat16*)g_B4;
#pragma unroll
    for (int r = 0; r < 4; r++) {
        int n = n0 + ty + r * 8;
        int k = k0 + tx;
        float w = t[tx][ty + r * 8];
        __nv_bfloat16 hi = __float2bfloat16_rn(w);
        __nv_bfloat16 lo = __float2bfloat16_rn(w - __bfloat162float(hi));
        size_t base = (size_t)n * FKP + k;
        Bg[base]        = hi;
        Bg[base + 1024] = lo;
    }
}

// ---------------------------------------------------------------------------
// Kernel 4: fusion GEMM, frag-level 3-term split over physical K=1024.
// out = Ahi*Bhi + Ahi*Blo + Alo*Bhi + bias.
// Block 128x128, 8 warps (32m x 64n), BK=32, cp.async double buffer.
// Dynamic smem: 8 tiles of [128][40] bf16 = 81920 B.
// ---------------------------------------------------------------------------
#define FT_BYTES (128 * 40 * 2)     // one tile
#define F_NC 32                      // chunks over physical K=1024

__global__ __launch_bounds__(256) void fuse_mma_kernel(
    const float* __restrict__ bfv, float* __restrict__ out)
{
    extern __shared__ __nv_bfloat16 fsm[];
    // tile order per buffer: Ah, Al, Bh, Bl
    __nv_bfloat16* tile[2][4];
#pragma unroll
    for (int bu = 0; bu < 2; bu++)
#pragma unroll
        for (int t = 0; t < 4; t++)
            tile[bu][t] = fsm + (bu * 4 + t) * (FT_BYTES / 2);

    const int tid = threadIdx.x;
    const int wid = tid >> 5;
    const int lane = tid & 31;
    const int bm = blockIdx.y * 128;
    const int bn = blockIdx.x * 128;
    const int wm = (wid >> 1) * 32;
    const int wn = (wid & 1) * 64;

    const __nv_bfloat16* Ag = (const __nv_bfloat16*)g_A4;
    const __nv_bfloat16* Bg = (const __nv_bfloat16*)g_B4;

    float acc[2][8][4];
#pragma unroll
    for (int mt = 0; mt < 2; mt++)
#pragma unroll
        for (int nt = 0; nt < 8; nt++)
#pragma unroll
            for (int r = 0; r < 4; r++) acc[mt][nt][r] = 0.f;

    // loader mapping: 512 16B-chunks per tile; 2 per thread
    auto load_chunk = [&](int c, int bu) {
#pragma unroll
        for (int i = 0; i < 2; i++) {
            int idx = tid * 2 + i;
            int row = idx >> 2;
            int c16 = idx & 3;
            uint32_t doff = row * 80 + c16 * 16;
            const __nv_bfloat16* arow = Ag + (size_t)(bm + row) * FKP + c * 32 + c16 * 8;
            const __nv_bfloat16* brow = Bg + (size_t)(bn + row) * FKP + c * 32 + c16 * 8;
            CP16(smem_u32(tile[bu][0]) + doff, arow);
            CP16(smem_u32(tile[bu][1]) + doff, arow + 1024);
            CP16(smem_u32(tile[bu][2]) + doff, brow);
            CP16(smem_u32(tile[bu][3]) + doff, brow + 1024);
        }
        CP_COMMIT();
    };

    load_chunk(0, 0);

    const int brow_off = ((lane >> 4) & 1) * 8 + (lane & 7);
    const int bk_off = ((lane >> 3) & 1) * 8;

    for (int c = 0; c < F_NC; c++) {
        const int bu = c & 1;
        CP_WAIT0();
        __syncthreads();
        if (c + 1 < F_NC) load_chunk(c + 1, bu ^ 1);

        const __nv_bfloat16* Ah = tile[bu][0];
        const __nv_bfloat16* Al = tile[bu][1];
        const __nv_bfloat16* Bh = tile[bu][2];
        const __nv_bfloat16* Bl = tile[bu][3];

#pragma unroll
        for (int ks = 0; ks < 2; ks++) {
            const int k0 = ks * 16;
            uint32_t ahf[2][4], alf[2][4];
#pragma unroll
            for (int mt = 0; mt < 2; mt++) {
                int r = wm + mt * 16 + (lane & 15);
                int kk = k0 + (lane >> 4) * 8;
                LDSM_X4(ahf[mt], smem_u32(Ah + r * 40 + kk));
                LDSM_X4(alf[mt], smem_u32(Al + r * 40 + kk));
            }
#pragma unroll
            for (int ntp = 0; ntp < 4; ntp++) {
                uint32_t bh4[4], bl4[4];
                int r = wn + ntp * 16 + brow_off;
                LDSM_X4(bh4, smem_u32(Bh + r * 40 + k0 + bk_off));
                LDSM_X4(bl4, smem_u32(Bl + r * 40 + k0 + bk_off));
#pragma unroll
                for (int mt = 0; mt < 2; mt++) {
                    mma_bf16(acc[mt][2 * ntp],     ahf[mt], bh4 + 0);
                    mma_bf16(acc[mt][2 * ntp],     ahf[mt], bl4 + 0);
                    mma_bf16(acc[mt][2 * ntp],     alf[mt], bh4 + 0);
                    mma_bf16(acc[mt][2 * ntp + 1], ahf[mt], bh4 + 2);
                    mma_bf16(acc[mt][2 * ntp + 1], ahf[mt], bl4 + 2);
                    mma_bf16(acc[mt][2 * ntp + 1], alf[mt], bh4 + 2);
                }
            }
        }
        __syncthreads();
    }

#pragma unroll
    for (int mt = 0; mt < 2; mt++) {
        const int row0 = bm + wm + mt * 16 + (lane >> 2);
#pragma unroll
        for (int nt = 0; nt < 8; nt++) {
            const int col = bn + wn + nt * 8 + (lane & 3) * 2;
            const float b0 = bfv[col], b1 = bfv[col + 1];
            float* p0 = out + (size_t)row0 * Dn + col;
            float* p1 = out + (size_t)(row0 + 8) * Dn + col;
            p0[0] = acc[mt][nt][0] + b0;
            p0[1] = acc[mt][nt][1] + b1;
            p1[0] = acc[mt][nt][2] + b0;
            p1[1] = acc[mt][nt][3] + b1;
        }
    }
}

// ---------------------------------------------------------------------------
extern "C" void kernel_launch(void* const* d_in, const int* in_sizes, int n_in,
                              void* d_out, int out_size)
{
    const float* X    = (const float*)d_in[0];
    const int*   mask = (const int*)  d_in[1];
    const float* Wq   = (const float*)d_in[2];
    const float* bq   = (const float*)d_in[3];
    const float* Wk   = (const float*)d_in[4];
    const float* bk   = (const float*)d_in[5];
    const float* Wv   = (const float*)d_in[6];
    const float* bv   = (const float*)d_in[7];
    const float* Wf   = (const float*)d_in[8];
    const float* bfp  = (const float*)d_in[9];
    float* out = (float*)d_out;

    static int smem_set = 0;
    if (!smem_set) {
        cudaFuncSetAttribute(fuse_mma_kernel,
                             cudaFuncAttributeMaxDynamicSharedMemorySize, 8 * FT_BYTES);
        smem_set = 1;
    }

    qkv_kernel<<<dim3(Bn * Hn, Tn / 64), 256>>>(X, Wq, bq, Wk, bk, Wv, bv);
    attn_mma_kernel<<<dim3(Bn * Hn, Tn / 64), 128>>>(mask);
    convw_kernel<<<dim3(Dn / 32, Dn / 32), 256>>>(Wf);
    fuse_mma_kernel<<<dim3(Dn / 128, (Bn * Tn) / 128), 256, 8 * FT_BYTES>>>(bfp, out);
}

// round 17
// speedup vs baseline: 1.1005x; 1.1005x over previous
#include <cuda_runtime.h>
#include <cuda_bf16.h>
#include <cstdint>

// Problem constants
#define Bn 8
#define Tn 512
#define Dn 1024
#define Hn 16
#define DHn 64
#define FKP 2048   // physical operand width: [hi | lo]

// Scratch (allocation-free __device__ globals; uint4 => 16B alignment)
__device__ uint4 g_A4[(size_t)Bn * Tn * FKP * 2 / 16];  // bf16 A [4096][2048]: hi|lo
__device__ uint4 g_B4[(size_t)Dn * FKP * 2 / 16];       // bf16 B [1024][2048]: hi|lo (Wf^T)
// Attention operands (bf16), per (b,h):
__device__ uint4 g_Qh4[Bn * Hn * Tn * DHn * 2 / 16];   // [bh][t][64] hi, pre-scaled 1/8
__device__ uint4 g_Ql4[Bn * Hn * Tn * DHn * 2 / 16];   // lo
__device__ uint4 g_Kh4[Bn * Hn * Tn * DHn * 2 / 16];   // [bh][t][64]
__device__ uint4 g_Kl4[Bn * Hn * Tn * DHn * 2 / 16];
__device__ uint4 g_Vh4[Bn * Hn * Tn * DHn * 2 / 16];   // [bh][d][t]  (transposed)
__device__ uint4 g_Vl4[Bn * Hn * Tn * DHn * 2 / 16];

__device__ __forceinline__ uint32_t smem_u32(const void* p) {
    uint32_t a;
    asm("{ .reg .u64 t; cvta.to.shared.u64 t, %1; cvt.u32.u64 %0, t; }" : "=r"(a) : "l"(p));
    return a;
}
__device__ __forceinline__ uint32_t pack_bf16(float a, float b) {
    __nv_bfloat162 t = __floats2bfloat162_rn(a, b);
    return *(uint32_t*)&t;
}
__device__ __forceinline__ void mma_bf16(float* c, const uint32_t* a, const uint32_t* b) {
    asm volatile(
        "mma.sync.aligned.m16n8k16.row.col.f32.bf16.bf16.f32 "
        "{%0,%1,%2,%3}, {%4,%5,%6,%7}, {%8,%9}, {%0,%1,%2,%3};"
        : "+f"(c[0]), "+f"(c[1]), "+f"(c[2]), "+f"(c[3])
        : "r"(a[0]), "r"(a[1]), "r"(a[2]), "r"(a[3]), "r"(b[0]), "r"(b[1]));
}
#define LDSM_X4(r, addr) \
    asm volatile("ldmatrix.sync.aligned.m8n8.x4.shared.b16 {%0,%1,%2,%3}, [%4];" \
                 : "=r"((r)[0]), "=r"((r)[1]), "=r"((r)[2]), "=r"((r)[3]) : "r"(addr))
#define CP16(dst, src) \
    asm volatile("cp.async.cg.shared.global [%0], [%1], 16;" :: "r"(dst), "l"(src))
#define CP_COMMIT() asm volatile("cp.async.commit_group;" ::: "memory")
#define CP_WAIT0()  asm volatile("cp.async.wait_group 0;" ::: "memory")

// ---------------------------------------------------------------------------
// Kernel 1: per-head QKV projections -> split-bf16 operands.
// ---------------------------------------------------------------------------
__global__ __launch_bounds__(256) void qkv_kernel(
    const float* __restrict__ X,
    const float* __restrict__ Wq, const float* __restrict__ bq,
    const float* __restrict__ Wk, const float* __restrict__ bk,
    const float* __restrict__ Wv, const float* __restrict__ bv)
{
    const int bh = blockIdx.x;
    const int b = bh >> 4;
    const int h = bh & 15;
    const int t0 = blockIdx.y * 64;
    const int tid = threadIdx.x;

    __shared__ float XsT[64][68];
    __shared__ float Ws[64][64];

#pragma unroll
    for (int i = 0; i < 4; i++) {
        int idx = tid + i * 256;
        int r = idx >> 4;
        int d4 = (idx & 15) << 2;
        float4 xv = *(const float4*)(X + (size_t)(b * Tn + t0 + r) * Dn + h * DHn + d4);
        XsT[d4 + 0][r] = xv.x; XsT[d4 + 1][r] = xv.y;
        XsT[d4 + 2][r] = xv.z; XsT[d4 + 3][r] = xv.w;
    }

    const int tx = tid & 15, ty = tid >> 4;
    const int r0 = ty * 4, c0 = tx * 4;

    const float* Wsrc[3] = { Wq + h * DHn * DHn, Wk + h * DHn * DHn, Wv + h * DHn * DHn };
    const float* bsrc[3] = { bq + h * DHn, bk + h * DHn, bv + h * DHn };

    for (int w = 0; w < 3; w++) {
        __syncthreads();
#pragma unroll
        for (int i = 0; i < 4; i++) {
            int idx = tid + i * 256;
            int d = idx >> 4;
            int e4 = (idx & 15) << 2;
            *(float4*)&Ws[d][e4] = *(const float4*)(Wsrc[w] + d * DHn + e4);
        }
        __syncthreads();

        float acc[4][4];
        float4 bv4 = *(const float4*)(bsrc[w] + c0);
#pragma unroll
        for (int i = 0; i < 4; i++) {
            acc[i][0] = bv4.x; acc[i][1] = bv4.y; acc[i][2] = bv4.z; acc[i][3] = bv4.w;
        }
#pragma unroll 8
        for (int d = 0; d < 64; d++) {
            float4 xr = *(float4*)&XsT[d][r0];
            float4 wr = *(float4*)&Ws[d][c0];
            float xa[4] = { xr.x, xr.y, xr.z, xr.w };
            float wa[4] = { wr.x, wr.y, wr.z, wr.w };
#pragma unroll
            for (int i = 0; i < 4; i++)
#pragma unroll
                for (int j = 0; j < 4; j++)
                    acc[i][j] += xa[i] * wa[j];
        }

        const float scale = (w == 0) ? 0.125f : 1.0f;
        if (w < 2) {
            __nv_bfloat16* dh = (__nv_bfloat16*)(w == 0 ? g_Qh4 : g_Kh4)
                                + ((size_t)bh * Tn + t0 + r0) * DHn + c0;
            __nv_bfloat16* dl = (__nv_bfloat16*)(w == 0 ? g_Ql4 : g_Kl4)
                                + ((size_t)bh * Tn + t0 + r0) * DHn + c0;
#pragma unroll
            for (int i = 0; i < 4; i++) {
#pragma unroll
                for (int j2 = 0; j2 < 2; j2++) {
                    float v0 = acc[i][j2 * 2 + 0] * scale;
                    float v1 = acc[i][j2 * 2 + 1] * scale;
                    __nv_bfloat16 h0 = __float2bfloat16_rn(v0);
                    __nv_bfloat16 h1 = __float2bfloat16_rn(v1);
                    __nv_bfloat162 hp; hp.x = h0; hp.y = h1;
                    __nv_bfloat162 lp;
                    lp.x = __float2bfloat16_rn(v0 - __bfloat162float(h0));
                    lp.y = __float2bfloat16_rn(v1 - __bfloat162float(h1));
                    *(__nv_bfloat162*)(dh + (size_t)i * DHn + j2 * 2) = hp;
                    *(__nv_bfloat162*)(dl + (size_t)i * DHn + j2 * 2) = lp;
                }
            }
        } else {
            __nv_bfloat16* vh = (__nv_bfloat16*)g_Vh4 + (size_t)bh * DHn * Tn;
            __nv_bfloat16* vl = (__nv_bfloat16*)g_Vl4 + (size_t)bh * DHn * Tn;
#pragma unroll
            for (int i = 0; i < 4; i++)
#pragma unroll
                for (int j = 0; j < 4; j++) {
                    float v = acc[i][j];
                    __nv_bfloat16 hi = __float2bfloat16_rn(v);
                    vh[(size_t)(c0 + j) * Tn + t0 + r0 + i] = hi;
                    vl[(size_t)(c0 + j) * Tn + t0 + r0 + i] =
                        __float2bfloat16_rn(v - __bfloat162float(hi));
                }
        }
    }
}

// ---------------------------------------------------------------------------
// Kernel 2: tensor-core flash attention, term-major mma issue (chains broken).
// grid = (B*H, T/64), block = 128 (4 warps x m16 queries).
// ---------------------------------------------------------------------------
__global__ __launch_bounds__(128) void attn_mma_kernel(const int* __restrict__ mask)
{
    const int bh = blockIdx.x;
    const int b = bh >> 4;
    const int h = bh & 15;
    const int q0 = blockIdx.y * 64;
    const int tid = threadIdx.x;
    const int wid = tid >> 5;
    const int lane = tid & 31;
    const int wm = wid * 16;

    __shared__ __nv_bfloat16 Khs[64][72];
    __shared__ __nv_bfloat16 Kls[64][72];
    __shared__ __nv_bfloat16 Vhs[64][72];
    __shared__ __nv_bfloat16 Vls[64][72];
    __shared__ float msk[64];

    // ---- stage Q tile into Khs/Kls, extract A fragments ----
    {
        const __nv_bfloat16* Qh = (const __nv_bfloat16*)g_Qh4 + ((size_t)bh * Tn + q0) * DHn;
        const __nv_bfloat16* Ql = (const __nv_bfloat16*)g_Ql4 + ((size_t)bh * Tn + q0) * DHn;
#pragma unroll
        for (int i = 0; i < 4; i++) {
            int idx = tid + i * 128;
            int row = idx >> 3;
            int c = idx & 7;
            *(uint4*)&Khs[row][c * 8] = *(const uint4*)(Qh + row * DHn + c * 8);
            *(uint4*)&Kls[row][c * 8] = *(const uint4*)(Ql + row * DHn + c * 8);
        }
    }
    __syncthreads();

    uint32_t qh[4][4], ql[4][4];
#pragma unroll
    for (int kt = 0; kt < 4; kt++) {
        LDSM_X4(qh[kt], smem_u32(&Khs[wm + (lane & 15)][kt * 16 + (lane >> 4) * 8]));
        LDSM_X4(ql[kt], smem_u32(&Kls[wm + (lane & 15)][kt * 16 + (lane >> 4) * 8]));
    }

    float O[8][4];
#pragma unroll
    for (int nt = 0; nt < 8; nt++)
#pragma unroll
        for (int r = 0; r < 4; r++) O[nt][r] = 0.f;
    float m0 = -1e30f, m1 = -1e30f, l0 = 0.f, l1 = 0.f;

    const __nv_bfloat16* Khg = (const __nv_bfloat16*)g_Kh4 + (size_t)bh * Tn * DHn;
    const __nv_bfloat16* Klg = (const __nv_bfloat16*)g_Kl4 + (size_t)bh * Tn * DHn;
    const __nv_bfloat16* Vhg = (const __nv_bfloat16*)g_Vh4 + (size_t)bh * DHn * Tn;
    const __nv_bfloat16* Vlg = (const __nv_bfloat16*)g_Vl4 + (size_t)bh * DHn * Tn;

    const int brow = ((lane >> 4) & 1) * 8 + (lane & 7);
    const int bkof = ((lane >> 3) & 1) * 8;

    for (int kt0 = 0; kt0 < 8; kt0++) {
        const int t0k = kt0 * 64;
        __syncthreads();
#pragma unroll
        for (int i = 0; i < 4; i++) {
            int idx = tid + i * 128;
            int row = idx >> 3;
            int c = idx & 7;
            *(uint4*)&Khs[row][c * 8] = *(const uint4*)(Khg + (size_t)(t0k + row) * DHn + c * 8);
            *(uint4*)&Kls[row][c * 8] = *(const uint4*)(Klg + (size_t)(t0k + row) * DHn + c * 8);
            *(uint4*)&Vhs[row][c * 8] = *(const uint4*)(Vhg + (size_t)row * Tn + t0k + c * 8);
            *(uint4*)&Vls[row][c * 8] = *(const uint4*)(Vlg + (size_t)row * Tn + t0k + c * 8);
        }
        if (tid < 64) msk[tid] = (mask[b * Tn + t0k + tid] > 0) ? 3.0e38f : -1e9f;
        __syncthreads();

        // ---- S = Q K^T (3-term, term-major issue over ntp pairs) ----
        float S[8][4];
#pragma unroll
        for (int nt = 0; nt < 8; nt++)
#pragma unroll
            for (int r = 0; r < 4; r++) S[nt][r] = 0.f;

#pragma unroll
        for (int kt = 0; kt < 4; kt++) {
#pragma unroll
            for (int np2 = 0; np2 < 2; np2++) {
                uint32_t kh4[2][4], kl4[2][4];
#pragma unroll
                for (int i = 0; i < 2; i++) {
                    int ntp = np2 * 2 + i;
                    LDSM_X4(kh4[i], smem_u32(&Khs[ntp * 16 + brow][kt * 16 + bkof]));
                    LDSM_X4(kl4[i], smem_u32(&Kls[ntp * 16 + brow][kt * 16 + bkof]));
                }
                float* s0 = S[np2 * 4 + 0];
                float* s1 = S[np2 * 4 + 1];
                float* s2 = S[np2 * 4 + 2];
                float* s3 = S[np2 * 4 + 3];
                // term hh (4 independent accs)
                mma_bf16(s0, qh[kt], kh4[0] + 0);
                mma_bf16(s1, qh[kt], kh4[0] + 2);
                mma_bf16(s2, qh[kt], kh4[1] + 0);
                mma_bf16(s3, qh[kt], kh4[1] + 2);
                // term lh
                mma_bf16(s0, ql[kt], kh4[0] + 0);
                mma_bf16(s1, ql[kt], kh4[0] + 2);
                mma_bf16(s2, ql[kt], kh4[1] + 0);
                mma_bf16(s3, ql[kt], kh4[1] + 2);
                // term hl
                mma_bf16(s0, qh[kt], kl4[0] + 0);
                mma_bf16(s1, qh[kt], kl4[0] + 2);
                mma_bf16(s2, qh[kt], kl4[1] + 0);
                mma_bf16(s3, qh[kt], kl4[1] + 2);
            }
        }

        // ---- mask + online softmax ----
        float rm0 = -1e30f, rm1 = -1e30f;
#pragma unroll
        for (int nt = 0; nt < 8; nt++) {
            int c = nt * 8 + 2 * (lane & 3);
            float mk0 = msk[c], mk1 = msk[c + 1];
            S[nt][0] = fminf(S[nt][0], mk0);
            S[nt][1] = fminf(S[nt][1], mk1);
            S[nt][2] = fminf(S[nt][2], mk0);
            S[nt][3] = fminf(S[nt][3], mk1);
            rm0 = fmaxf(rm0, fmaxf(S[nt][0], S[nt][1]));
            rm1 = fmaxf(rm1, fmaxf(S[nt][2], S[nt][3]));
        }
        rm0 = fmaxf(rm0, __shfl_xor_sync(0xffffffffu, rm0, 1));
        rm0 = fmaxf(rm0, __shfl_xor_sync(0xffffffffu, rm0, 2));
        rm1 = fmaxf(rm1, __shfl_xor_sync(0xffffffffu, rm1, 1));
        rm1 = fmaxf(rm1, __shfl_xor_sync(0xffffffffu, rm1, 2));

        float m0n = fmaxf(m0, rm0), m1n = fmaxf(m1, rm1);
        float c0f = __expf(m0 - m0n), c1f = __expf(m1 - m1n);
        l0 *= c0f; l1 *= c1f;
#pragma unroll
        for (int nt = 0; nt < 8; nt++) {
            O[nt][0] *= c0f; O[nt][1] *= c0f;
            O[nt][2] *= c1f; O[nt][3] *= c1f;
        }
        m0 = m0n; m1 = m1n;

        float ps0 = 0.f, ps1 = 0.f;
#pragma unroll
        for (int nt = 0; nt < 8; nt++) {
            S[nt][0] = __expf(S[nt][0] - m0);
            S[nt][1] = __expf(S[nt][1] - m0);
            S[nt][2] = __expf(S[nt][2] - m1);
            S[nt][3] = __expf(S[nt][3] - m1);
            ps0 += S[nt][0] + S[nt][1];
            ps1 += S[nt][2] + S[nt][3];
        }
        l0 += ps0; l1 += ps1;

        // ---- O += P V (3-term, term-major over ntp pairs) ----
#pragma unroll
        for (int kt = 0; kt < 4; kt++) {
            float p00 = S[2 * kt][0], p01 = S[2 * kt][1], p02 = S[2 * kt][2], p03 = S[2 * kt][3];
            float p10 = S[2 * kt + 1][0], p11 = S[2 * kt + 1][1], p12 = S[2 * kt + 1][2], p13 = S[2 * kt + 1][3];
            __nv_bfloat16 h00 = __float2bfloat16_rn(p00), h01 = __float2bfloat16_rn(p01);
            __nv_bfloat16 h02 = __float2bfloat16_rn(p02), h03 = __float2bfloat16_rn(p03);
            __nv_bfloat16 h10 = __float2bfloat16_rn(p10), h11 = __float2bfloat16_rn(p11);
            __nv_bfloat16 h12 = __float2bfloat16_rn(p12), h13 = __float2bfloat16_rn(p13);
            uint32_t ah[4], al[4];
            { __nv_bfloat162 t; t.x = h00; t.y = h01; ah[0] = *(uint32_t*)&t; }
            { __nv_bfloat162 t; t.x = h02; t.y = h03; ah[1] = *(uint32_t*)&t; }
            { __nv_bfloat162 t; t.x = h10; t.y = h11; ah[2] = *(uint32_t*)&t; }
            { __nv_bfloat162 t; t.x = h12; t.y = h13; ah[3] = *(uint32_t*)&t; }
            al[0] = pack_bf16(p00 - __bfloat162float(h00), p01 - __bfloat162float(h01));
            al[1] = pack_bf16(p02 - __bfloat162float(h02), p03 - __bfloat162float(h03));
            al[2] = pack_bf16(p10 - __bfloat162float(h10), p11 - __bfloat162float(h11));
            al[3] = pack_bf16(p12 - __bfloat162float(h12), p13 - __bfloat162float(h13));
#pragma unroll
            for (int np2 = 0; np2 < 2; np2++) {
                uint32_t vh4[2][4], vl4[2][4];
#pragma unroll
                for (int i = 0; i < 2; i++) {
                    int ntp = np2 * 2 + i;
                    LDSM_X4(vh4[i], smem_u32(&Vhs[ntp * 16 + brow][kt * 16 + bkof]));
                    LDSM_X4(vl4[i], smem_u32(&Vls[ntp * 16 + brow][kt * 16 + bkof]));
                }
                float* o0 = O[np2 * 4 + 0];
                float* o1 = O[np2 * 4 + 1];
                float* o2 = O[np2 * 4 + 2];
                float* o3 = O[np2 * 4 + 3];
                // term hh
                mma_bf16(o0, ah, vh4[0] + 0);
                mma_bf16(o1, ah, vh4[0] + 2);
                mma_bf16(o2, ah, vh4[1] + 0);
                mma_bf16(o3, ah, vh4[1] + 2);
                // term lh (Plo x Vhi)
                mma_bf16(o0, al, vh4[0] + 0);
                mma_bf16(o1, al, vh4[0] + 2);
                mma_bf16(o2, al, vh4[1] + 0);
                mma_bf16(o3, al, vh4[1] + 2);
                // term hl (Phi x Vlo)
                mma_bf16(o0, ah, vl4[0] + 0);
                mma_bf16(o1, ah, vl4[0] + 2);
                mma_bf16(o2, ah, vl4[1] + 0);
                mma_bf16(o3, ah, vl4[1] + 2);
            }
        }
    }

    // ---- epilogue ----
    l0 += __shfl_xor_sync(0xffffffffu, l0, 1);
    l0 += __shfl_xor_sync(0xffffffffu, l0, 2);
    l1 += __shfl_xor_sync(0xffffffffu, l1, 1);
    l1 += __shfl_xor_sync(0xffffffffu, l1, 2);
    const float inv0 = 1.f / l0;
    const float inv1 = 1.f / l1;

    const int row0 = b * Tn + q0 + wm + (lane >> 2);
    const int row1 = row0 + 8;
    __nv_bfloat16* Ap = (__nv_bfloat16*)g_A4;
#pragma unroll
    for (int nt = 0; nt < 8; nt++) {
        const int col = h * DHn + nt * 8 + 2 * (lane & 3);
        float o00 = O[nt][0] * inv0, o01 = O[nt][1] * inv0;
        float o10 = O[nt][2] * inv1, o11 = O[nt][3] * inv1;
        __nv_bfloat16 h00 = __float2bfloat16_rn(o00), h01 = __float2bfloat16_rn(o01);
        __nv_bfloat16 h10 = __float2bfloat16_rn(o10), h11 = __float2bfloat16_rn(o11);
        uint32_t hp0, hp1;
        { __nv_bfloat162 t; t.x = h00; t.y = h01; hp0 = *(uint32_t*)&t; }
        { __nv_bfloat162 t; t.x = h10; t.y = h11; hp1 = *(uint32_t*)&t; }
        uint32_t lp0 = pack_bf16(o00 - __bfloat162float(h00), o01 - __bfloat162float(h01));
        uint32_t lp1 = pack_bf16(o10 - __bfloat162float(h10), o11 - __bfloat162float(h11));
        *(uint32_t*)(Ap + (size_t)row0 * FKP + col)        = hp0;
        *(uint32_t*)(Ap + (size_t)row0 * FKP + 1024 + col) = lp0;
        *(uint32_t*)(Ap + (size_t)row1 * FKP + col)        = hp1;
        *(uint32_t*)(Ap + (size_t)row1 * FKP + 1024 + col) = lp1;
    }
}

// ---------------------------------------------------------------------------
// Kernel 3: build B = split-bf16 transpose of Wf: hi at k, lo at 1024+k.
// ---------------------------------------------------------------------------
__global__ __launch_bounds__(256) void convw_kernel(const float* __restrict__ Wf)
{
    __shared__ float t[32][33];
    const int tx = threadIdx.x & 31, ty = threadIdx.x >> 5;
    const int n0 = blockIdx.x * 32, k0 = blockIdx.y * 32;

#pragma unroll
    for (int r = 0; r < 4; r++)
        t[ty + r * 8][tx] = Wf[(size_t)(k0 + ty + r * 8) * Dn + n0 + tx];
    __syncthreads();

    __nv_bfloat16* Bg = (__nv_bfloat16*)g_B4;
#pragma unroll
    for (int r = 0; r < 4; r++) {
        int n = n0 + ty + r * 8;
        int k = k0 + tx;
        float w = t[tx][ty + r * 8];
        __nv_bfloat16 hi = __float2bfloat16_rn(w);
        __nv_bfloat16 lo = __float2bfloat16_rn(w - __bfloat162float(hi));
        size_t base = (size_t)n * FKP + k;
        Bg[base]        = hi;
        Bg[base + 1024] = lo;
    }
}

// ---------------------------------------------------------------------------
// Kernel 4: fusion GEMM, frag-level 3-term split, term-major mma issue.
// Block 128x128, 8 warps (32m x 64n), BK=32, cp.async double buffer.
// ---------------------------------------------------------------------------
#define FT_BYTES (128 * 40 * 2)
#define F_NC 32

__global__ __launch_bounds__(256) void fuse_mma_kernel(
    const float* __restrict__ bfv, float* __restrict__ out)
{
    extern __shared__ __nv_bfloat16 fsm[];
    __nv_bfloat16* tile[2][4];
#pragma unroll
    for (int bu = 0; bu < 2; bu++)
#pragma unroll
        for (int t = 0; t < 4; t++)
            tile[bu][t] = fsm + (bu * 4 + t) * (FT_BYTES / 2);

    const int tid = threadIdx.x;
    const int wid = tid >> 5;
    const int lane = tid & 31;
    const int bm = blockIdx.y * 128;
    const int bn = blockIdx.x * 128;
    const int wm = (wid >> 1) * 32;
    const int wn = (wid & 1) * 64;

    const __nv_bfloat16* Ag = (const __nv_bfloat16*)g_A4;
    const __nv_bfloat16* Bg = (const __nv_bfloat16*)g_B4;

    float acc[2][8][4];
#pragma unroll
    for (int mt = 0; mt < 2; mt++)
#pragma unroll
        for (int nt = 0; nt < 8; nt++)
#pragma unroll
            for (int r = 0; r < 4; r++) acc[mt][nt][r] = 0.f;

    auto load_chunk = [&](int c, int bu) {
#pragma unroll
        for (int i = 0; i < 2; i++) {
            int idx = tid * 2 + i;
            int row = idx >> 2;
            int c16 = idx & 3;
            uint32_t doff = row * 80 + c16 * 16;
            const __nv_bfloat16* arow = Ag + (size_t)(bm + row) * FKP + c * 32 + c16 * 8;
            const __nv_bfloat16* brow = Bg + (size_t)(bn + row) * FKP + c * 32 + c16 * 8;
            CP16(smem_u32(tile[bu][0]) + doff, arow);
            CP16(smem_u32(tile[bu][1]) + doff, arow + 1024);
            CP16(smem_u32(tile[bu][2]) + doff, brow);
            CP16(smem_u32(tile[bu][3]) + doff, brow + 1024);
        }
        CP_COMMIT();
    };

    load_chunk(0, 0);

    const int brow_off = ((lane >> 4) & 1) * 8 + (lane & 7);
    const int bk_off = ((lane >> 3) & 1) * 8;

    for (int c = 0; c < F_NC; c++) {
        const int bu = c & 1;
        CP_WAIT0();
        __syncthreads();
        if (c + 1 < F_NC) load_chunk(c + 1, bu ^ 1);

        const __nv_bfloat16* Ah = tile[bu][0];
        const __nv_bfloat16* Al = tile[bu][1];
        const __nv_bfloat16* Bh = tile[bu][2];
        const __nv_bfloat16* Bl = tile[bu][3];

#pragma unroll
        for (int ks = 0; ks < 2; ks++) {
            const int k0 = ks * 16;
            uint32_t ahf[2][4], alf[2][4];
#pragma unroll
            for (int mt = 0; mt < 2; mt++) {
                int r = wm + mt * 16 + (lane & 15);
                int kk = k0 + (lane >> 4) * 8;
                LDSM_X4(ahf[mt], smem_u32(Ah + r * 40 + kk));
                LDSM_X4(alf[mt], smem_u32(Al + r * 40 + kk));
            }
            uint32_t bh4[4][4], bl4[4][4];
#pragma unroll
            for (int ntp = 0; ntp < 4; ntp++) {
                int r = wn + ntp * 16 + brow_off;
                LDSM_X4(bh4[ntp], smem_u32(Bh + r * 40 + k0 + bk_off));
                LDSM_X4(bl4[ntp], smem_u32(Bl + r * 40 + k0 + bk_off));
            }
            // term hh: 16 independent accumulators
#pragma unroll
            for (int mt = 0; mt < 2; mt++)
#pragma unroll
                for (int ntp = 0; ntp < 4; ntp++) {
                    mma_bf16(acc[mt][2 * ntp],     ahf[mt], bh4[ntp] + 0);
                    mma_bf16(acc[mt][2 * ntp + 1], ahf[mt], bh4[ntp] + 2);
                }
            // term hl
#pragma unroll
            for (int mt = 0; mt < 2; mt++)
#pragma unroll
                for (int ntp = 0; ntp < 4; ntp++) {
                    mma_bf16(acc[mt][2 * ntp],     ahf[mt], bl4[ntp] + 0);
                    mma_bf16(acc[mt][2 * ntp + 1], ahf[mt], bl4[ntp] + 2);
                }
            // term lh
#pragma unroll
            for (int mt = 0; mt < 2; mt++)
#pragma unroll
                for (int ntp = 0; ntp < 4; ntp++) {
                    mma_bf16(acc[mt][2 * ntp],     alf[mt], bh4[ntp] + 0);
                    mma_bf16(acc[mt][2 * ntp + 1], alf[mt], bh4[ntp] + 2);
                }
        }
        __syncthreads();
    }

#pragma unroll
    for (int mt = 0; mt < 2; mt++) {
        const int row0 = bm + wm + mt * 16 + (lane >> 2);
#pragma unroll
        for (int nt = 0; nt < 8; nt++) {
            const int col = bn + wn + nt * 8 + (lane & 3) * 2;
            const float b0 = bfv[col], b1 = bfv[col + 1];
            float* p0 = out + (size_t)row0 * Dn + col;
            float* p1 = out + (size_t)(row0 + 8) * Dn + col;
            p0[0] = acc[mt][nt][0] + b0;
            p0[1] = acc[mt][nt][1] + b1;
            p1[0] = acc[mt][nt][2] + b0;
            p1[1] = acc[mt][nt][3] + b1;
        }
    }
}

// ---------------------------------------------------------------------------
extern "C" void kernel_launch(void* const* d_in, const int* in_sizes, int n_in,
                              void* d_out, int out_size)
{
    const float* X    = (const float*)d_in[0];
    const int*   mask = (const int*)  d_in[1];
    const float* Wq   = (const float*)d_in[2];
    const float* bq   = (const float*)d_in[3];
    const float* Wk   = (const float*)d_in[4];
    const float* bk   = (const float*)d_in[5];
    const float* Wv   = (const float*)d_in[6];
    const float* bv   = (const float*)d_in[7];
    const float* Wf   = (const float*)d_in[8];
    const float* bfp  = (const float*)d_in[9];
    float* out = (float*)d_out;

    static int smem_set = 0;
    if (!smem_set) {
        cudaFuncSetAttribute(fuse_mma_kernel,
                             cudaFuncAttributeMaxDynamicSharedMemorySize, 8 * FT_BYTES);
        smem_set = 1;
    }

    qkv_kernel<<<dim3(Bn * Hn, Tn / 64), 256>>>(X, Wq, bq, Wk, bk, Wv, bv);
    attn_mma_kernel<<<dim3(Bn * Hn, Tn / 64), 128>>>(mask);
    convw_kernel<<<dim3(Dn / 32, Dn / 32), 256>>>(Wf);
    fuse_mma_kernel<<<dim3(Dn / 128, (Bn * Tn) / 128), 256, 8 * FT_BYTES>>>(bfp, out);
}